// round 14
// baseline (speedup 1.0000x reference)
#include <cuda_runtime.h>

#define NE 64
#define NH 2048
#define NF 1408
#define NM 16

typedef unsigned long long ull;

// SwiGLU intermediate scratch: [E, M, F] fp32 = 5.77 MB
__device__ float g_inter[(size_t)NE * NM * NF];
// gate/up partial sums: [half(2) x mat(2)][E, M, F] fp32 = 23 MB
__device__ float g_pgu[(size_t)4 * NE * NM * NF];
// down-proj partial sums: [2, E, M, H] fp32 = 16.8 MB
__device__ float g_part[(size_t)2 * NE * NM * NH];

__device__ __forceinline__ ull pack2(float lo, float hi) {
    ull r;
    asm("mov.b64 %0, {%1, %2};" : "=l"(r) : "f"(lo), "f"(hi));
    return r;
}
__device__ __forceinline__ void fma2(ull& d, ull a, ull b) {
    asm("fma.rn.f32x2 %0, %1, %2, %0;" : "+l"(d) : "l"(a), "l"(b));
}
__device__ __forceinline__ float2 unpack2(ull v) {
    float2 r;
    asm("mov.b64 {%0, %1}, %2;" : "=f"(r.x), "=f"(r.y) : "l"(v));
    return r;
}

#define XS_PAD 20   // 80B row stride, 16B-aligned for LDS.128

// ---------------------------------------------------------------------------
// Kernel 1: partial gate/up accumulation over half of H.
// 64 thr/CTA, 2 f-cols/thread, TRIPLE-buffered depth-4 weight prefetch
// (prefetch distance 2 -> 2 batches of 8 LDG.64 in flight during compute).
// grid (11, 64, 2).
// ---------------------------------------------------------------------------
#define K1_HSPLIT 1024
#define K1_CHUNK 256
#define K1_NB (K1_CHUNK / 4)     // 64 blocks of 4 h-steps
#define K1_NT ((K1_NB - 1) / 3)  // 21 triples; tail block = 3*K1_NT

#define K1_COMP(gv, uv, hrow) do {                                             \
    ull bg0 = pack2((gv).x, (gv).x), bg1 = pack2((gv).y, (gv).y);              \
    ull bu0 = pack2((uv).x, (uv).x), bu1 = pack2((uv).y, (uv).y);              \
    const ulonglong2* xr = reinterpret_cast<const ulonglong2*>(&xs[hrow][0]);  \
    ulonglong2 x01 = xr[0], x23 = xr[1], x45 = xr[2], x67 = xr[3];             \
    fma2(accg[0][0], x01.x, bg0); fma2(accg[1][0], x01.x, bg1);                \
    fma2(accu[0][0], x01.x, bu0); fma2(accu[1][0], x01.x, bu1);                \
    fma2(accg[0][1], x01.y, bg0); fma2(accg[1][1], x01.y, bg1);                \
    fma2(accu[0][1], x01.y, bu0); fma2(accu[1][1], x01.y, bu1);                \
    fma2(accg[0][2], x23.x, bg0); fma2(accg[1][2], x23.x, bg1);                \
    fma2(accu[0][2], x23.x, bu0); fma2(accu[1][2], x23.x, bu1);                \
    fma2(accg[0][3], x23.y, bg0); fma2(accg[1][3], x23.y, bg1);                \
    fma2(accu[0][3], x23.y, bu0); fma2(accu[1][3], x23.y, bu1);                \
    fma2(accg[0][4], x45.x, bg0); fma2(accg[1][4], x45.x, bg1);                \
    fma2(accu[0][4], x45.x, bu0); fma2(accu[1][4], x45.x, bu1);                \
    fma2(accg[0][5], x45.y, bg0); fma2(accg[1][5], x45.y, bg1);                \
    fma2(accu[0][5], x45.y, bu0); fma2(accu[1][5], x45.y, bu1);                \
    fma2(accg[0][6], x67.x, bg0); fma2(accg[1][6], x67.x, bg1);                \
    fma2(accu[0][6], x67.x, bu0); fma2(accu[1][6], x67.x, bu1);                \
    fma2(accg[0][7], x67.y, bg0); fma2(accg[1][7], x67.y, bg1);                \
    fma2(accu[0][7], x67.y, bu0); fma2(accu[1][7], x67.y, bu1);                \
} while (0)

#define K1_LOAD(i, blk) do {                                                   \
    const int _b = (blk) < K1_NB ? (blk) : K1_NB - 1;                          \
    const float* _g = g0 + (size_t)(_b * 4) * NF;                              \
    const float* _u = u0 + (size_t)(_b * 4) * NF;                              \
    gb[i][0] = __ldg((const float2*)(_g));                                     \
    ub[i][0] = __ldg((const float2*)(_u));                                     \
    gb[i][1] = __ldg((const float2*)(_g + (size_t)1 * NF));                    \
    ub[i][1] = __ldg((const float2*)(_u + (size_t)1 * NF));                    \
    gb[i][2] = __ldg((const float2*)(_g + (size_t)2 * NF));                    \
    ub[i][2] = __ldg((const float2*)(_u + (size_t)2 * NF));                    \
    gb[i][3] = __ldg((const float2*)(_g + (size_t)3 * NF));                    \
    ub[i][3] = __ldg((const float2*)(_u + (size_t)3 * NF));                    \
} while (0)

#define K1_BLOCK(i, blk) do {                                                  \
    const int _hb = (blk) * 4;                                                 \
    K1_COMP(gb[i][0], ub[i][0], _hb + 0);                                      \
    K1_COMP(gb[i][1], ub[i][1], _hb + 1);                                      \
    K1_COMP(gb[i][2], ub[i][2], _hb + 2);                                      \
    K1_COMP(gb[i][3], ub[i][3], _hb + 3);                                      \
} while (0)

__global__ __launch_bounds__(64) void moe_gateup_kernel(
    const float* __restrict__ x,
    const float* __restrict__ gate,
    const float* __restrict__ up)
{
    __shared__ float xs[K1_CHUNK][XS_PAD];

    const int e = blockIdx.y;
    const int z = blockIdx.z;
    const int f = blockIdx.x * 128 + threadIdx.x * 2;

    const float* xe = x + (size_t)e * NM * NH + (size_t)z * K1_HSPLIT;
    const float* gp = gate + (size_t)e * NH * NF + (size_t)z * K1_HSPLIT * NF + f;
    const float* upp = up + (size_t)e * NH * NF + (size_t)z * K1_HSPLIT * NF + f;

    ull accg[2][8], accu[2][8];
#pragma unroll
    for (int c = 0; c < 2; c++)
#pragma unroll
        for (int j = 0; j < 8; j++) { accg[c][j] = 0ull; accu[c][j] = 0ull; }

    for (int hc = 0; hc < K1_HSPLIT; hc += K1_CHUNK) {
        __syncthreads();
#pragma unroll
        for (int mm = 0; mm < NM; mm++) {
#pragma unroll
            for (int hh = threadIdx.x; hh < K1_CHUNK; hh += 64)
                xs[hh][mm] = xe[(size_t)mm * NH + hc + hh];
        }
        __syncthreads();

        const float* g0 = gp + (size_t)hc * NF;
        const float* u0 = upp + (size_t)hc * NF;

        float2 gb[3][4], ub[3][4];
        K1_LOAD(0, 0);
        K1_LOAD(1, 1);

        for (int p = 0; p < K1_NT; p++) {
            const int b = 3 * p;
            K1_LOAD(2, b + 2);
            K1_BLOCK(0, b);
            K1_LOAD(0, b + 3);
            K1_BLOCK(1, b + 1);
            K1_LOAD(1, b + 4);
            K1_BLOCK(2, b + 2);
        }
        K1_BLOCK(0, 3 * K1_NT);   // tail block (lives in buf0)
    }

    // write partials: slot (z*2 + 0) = gate, (z*2 + 1) = up
    const size_t S = (size_t)NE * NM * NF;
    float* pg = g_pgu + (size_t)(z * 2 + 0) * S + (size_t)e * NM * NF + f;
    float* pu = g_pgu + (size_t)(z * 2 + 1) * S + (size_t)e * NM * NF + f;
#pragma unroll
    for (int j = 0; j < 8; j++) {
        float2 g0v = unpack2(accg[0][j]), g1v = unpack2(accg[1][j]);
        float2 u0v = unpack2(accu[0][j]), u1v = unpack2(accu[1][j]);
        float2 gm0 = make_float2(g0v.x, g1v.x);
        float2 gm1 = make_float2(g0v.y, g1v.y);
        float2 um0 = make_float2(u0v.x, u1v.x);
        float2 um1 = make_float2(u0v.y, u1v.y);
        *reinterpret_cast<float2*>(pg + (size_t)(2 * j) * NF)     = gm0;
        *reinterpret_cast<float2*>(pg + (size_t)(2 * j + 1) * NF) = gm1;
        *reinterpret_cast<float2*>(pu + (size_t)(2 * j) * NF)     = um0;
        *reinterpret_cast<float2*>(pu + (size_t)(2 * j + 1) * NF) = um1;
    }
}

// ---------------------------------------------------------------------------
// Kernel 1b: inter = silu(g0+g1) * (u0+u1)
// ---------------------------------------------------------------------------
__global__ __launch_bounds__(256) void moe_silu_kernel()
{
    const size_t S = (size_t)NE * NM * NF;
    const size_t n4 = S / 4;
    const size_t i = (size_t)blockIdx.x * 256 + threadIdx.x;
    if (i < n4) {
        const float4* G0 = reinterpret_cast<const float4*>(g_pgu + 0 * S);
        const float4* U0 = reinterpret_cast<const float4*>(g_pgu + 1 * S);
        const float4* G1 = reinterpret_cast<const float4*>(g_pgu + 2 * S);
        const float4* U1 = reinterpret_cast<const float4*>(g_pgu + 3 * S);
        float4 ga = G0[i], gb = G1[i], ua = U0[i], ub = U1[i];
        float gx = ga.x + gb.x, gy = ga.y + gb.y, gz = ga.z + gb.z, gw = ga.w + gb.w;
        float ux = ua.x + ub.x, uy = ua.y + ub.y, uz = ua.z + ub.z, uw = ua.w + ub.w;
        float4 r;
        r.x = gx / (1.0f + __expf(-gx)) * ux;
        r.y = gy / (1.0f + __expf(-gy)) * uy;
        r.z = gz / (1.0f + __expf(-gz)) * uz;
        r.w = gw / (1.0f + __expf(-gw)) * uw;
        reinterpret_cast<float4*>(g_inter)[i] = r;
    }
}

// ---------------------------------------------------------------------------
// Kernel 2: partial down-proj.  64 thr/CTA, 4 h-cols/thread, F-split 2,
// TRIPLE-buffered depth-4 LDG.128 weight prefetch.  grid (8, 64, 2).
// ---------------------------------------------------------------------------
#define K2_CHUNK 352
#define K2_FSPLIT 704
#define K2_NB (K2_CHUNK / 4)     // 88
#define K2_NT ((K2_NB - 1) / 3)  // 29 triples; tail block = 3*K2_NT = 87

#define K2_COMP(wv, hrow) do {                                                 \
    ull b0 = pack2((wv).x, (wv).x), b1w = pack2((wv).y, (wv).y);               \
    ull b2w = pack2((wv).z, (wv).z), b3 = pack2((wv).w, (wv).w);               \
    const ulonglong2* xr = reinterpret_cast<const ulonglong2*>(&xs[hrow][0]);  \
    ulonglong2 x01 = xr[0], x23 = xr[1], x45 = xr[2], x67 = xr[3];             \
    fma2(acc[0][0], x01.x, b0);  fma2(acc[1][0], x01.x, b1w);                  \
    fma2(acc[2][0], x01.x, b2w); fma2(acc[3][0], x01.x, b3);                   \
    fma2(acc[0][1], x01.y, b0);  fma2(acc[1][1], x01.y, b1w);                  \
    fma2(acc[2][1], x01.y, b2w); fma2(acc[3][1], x01.y, b3);                   \
    fma2(acc[0][2], x23.x, b0);  fma2(acc[1][2], x23.x, b1w);                  \
    fma2(acc[2][2], x23.x, b2w); fma2(acc[3][2], x23.x, b3);                   \
    fma2(acc[0][3], x23.y, b0);  fma2(acc[1][3], x23.y, b1w);                  \
    fma2(acc[2][3], x23.y, b2w); fma2(acc[3][3], x23.y, b3);                   \
    fma2(acc[0][4], x45.x, b0);  fma2(acc[1][4], x45.x, b1w);                  \
    fma2(acc[2][4], x45.x, b2w); fma2(acc[3][4], x45.x, b3);                   \
    fma2(acc[0][5], x45.y, b0);  fma2(acc[1][5], x45.y, b1w);                  \
    fma2(acc[2][5], x45.y, b2w); fma2(acc[3][5], x45.y, b3);                   \
    fma2(acc[0][6], x67.x, b0);  fma2(acc[1][6], x67.x, b1w);                  \
    fma2(acc[2][6], x67.x, b2w); fma2(acc[3][6], x67.x, b3);                   \
    fma2(acc[0][7], x67.y, b0);  fma2(acc[1][7], x67.y, b1w);                  \
    fma2(acc[2][7], x67.y, b2w); fma2(acc[3][7], x67.y, b3);                   \
} while (0)

#define K2_LOAD(i, blk) do {                                                   \
    const int _b = (blk) < K2_NB ? (blk) : K2_NB - 1;                          \
    const float* _d = d0 + (size_t)(_b * 4) * NH;                              \
    wb[i][0] = __ldg((const float4*)(_d));                                     \
    wb[i][1] = __ldg((const float4*)(_d + (size_t)1 * NH));                    \
    wb[i][2] = __ldg((const float4*)(_d + (size_t)2 * NH));                    \
    wb[i][3] = __ldg((const float4*)(_d + (size_t)3 * NH));                    \
} while (0)

#define K2_BLOCK(i, blk) do {                                                  \
    const int _hb = (blk) * 4;                                                 \
    K2_COMP(wb[i][0], _hb + 0);                                                \
    K2_COMP(wb[i][1], _hb + 1);                                                \
    K2_COMP(wb[i][2], _hb + 2);                                                \
    K2_COMP(wb[i][3], _hb + 3);                                                \
} while (0)

__global__ __launch_bounds__(64) void moe_down_kernel(
    const float* __restrict__ down)
{
    __shared__ float xs[K2_CHUNK][XS_PAD];

    const int e = blockIdx.y;
    const int z = blockIdx.z;
    const int h0 = blockIdx.x * 256 + threadIdx.x * 4;

    const float* ie = g_inter + (size_t)e * NM * NF + (size_t)z * K2_FSPLIT;
    const float* dp = down + (size_t)e * NF * NH + (size_t)z * K2_FSPLIT * NH + h0;

    ull acc[4][8];
#pragma unroll
    for (int c = 0; c < 4; c++)
#pragma unroll
        for (int j = 0; j < 8; j++) acc[c][j] = 0ull;

    for (int fc = 0; fc < K2_FSPLIT; fc += K2_CHUNK) {
        __syncthreads();
#pragma unroll
        for (int mm = 0; mm < NM; mm++) {
            for (int hh = threadIdx.x; hh < K2_CHUNK; hh += 64)
                xs[hh][mm] = ie[(size_t)mm * NF + fc + hh];
        }
        __syncthreads();

        const float* d0 = dp + (size_t)fc * NH;

        float4 wb[3][4];
        K2_LOAD(0, 0);
        K2_LOAD(1, 1);

        for (int p = 0; p < K2_NT; p++) {
            const int b = 3 * p;
            K2_LOAD(2, b + 2);
            K2_BLOCK(0, b);
            K2_LOAD(0, b + 3);
            K2_BLOCK(1, b + 1);
            K2_LOAD(1, b + 4);
            K2_BLOCK(2, b + 2);
        }
        K2_BLOCK(0, 3 * K2_NT);   // tail block (lives in buf0)
    }

    float* pp = g_part + ((size_t)z * NE * NM + (size_t)e * NM) * NH + h0;
#pragma unroll
    for (int j = 0; j < 8; j++) {
        float2 r0 = unpack2(acc[0][j]), r1 = unpack2(acc[1][j]);
        float2 r2 = unpack2(acc[2][j]), r3 = unpack2(acc[3][j]);
        float4 v0 = make_float4(r0.x, r1.x, r2.x, r3.x);
        float4 v1 = make_float4(r0.y, r1.y, r2.y, r3.y);
        *reinterpret_cast<float4*>(pp + (size_t)(2 * j) * NH)     = v0;
        *reinterpret_cast<float4*>(pp + (size_t)(2 * j + 1) * NH) = v1;
    }
}

// ---------------------------------------------------------------------------
// Kernel 3: out = part[0] + part[1]
// ---------------------------------------------------------------------------
__global__ __launch_bounds__(256) void moe_reduce_kernel(float* __restrict__ out)
{
    const size_t i = (size_t)blockIdx.x * 256 + threadIdx.x;   // float4 index
    const size_t n4 = (size_t)NE * NM * NH / 4;
    if (i < n4) {
        const float4* p0 = reinterpret_cast<const float4*>(g_part);
        const float4* p1 = reinterpret_cast<const float4*>(g_part + (size_t)NE * NM * NH);
        float4 a = p0[i], b = p1[i];
        float4 r = make_float4(a.x + b.x, a.y + b.y, a.z + b.z, a.w + b.w);
        reinterpret_cast<float4*>(out)[i] = r;
    }
}

extern "C" void kernel_launch(void* const* d_in, const int* in_sizes, int n_in,
                              void* d_out, int out_size)
{
    const float* x    = (const float*)d_in[0];  // [T=1024, H=2048]
    const float* gate = (const float*)d_in[1];  // [E, H, F]
    const float* up   = (const float*)d_in[2];  // [E, H, F]
    const float* down = (const float*)d_in[3];  // [E, F, H]
    float* out = (float*)d_out;                 // [T, H] fp32

    dim3 g1(NF / 128, NE, 2);     // 11 x 64 x 2 = 1408 CTAs, 64 thr
    moe_gateup_kernel<<<g1, 64>>>(x, gate, up);

    const int nS4 = NE * NM * NF / 4;             // 360448
    moe_silu_kernel<<<(nS4 + 255) / 256, 256>>>();

    dim3 g2(NH / 256, NE, 2);     // 8 x 64 x 2 = 1024 CTAs, 64 thr
    moe_down_kernel<<<g2, 64>>>(down);

    const int n4 = NE * NM * NH / 4;              // 524288
    moe_reduce_kernel<<<(n4 + 255) / 256, 256>>>(out);
}

// round 15
// speedup vs baseline: 1.0596x; 1.0596x over previous
#include <cuda_runtime.h>

#define NE 64
#define NH 2048
#define NF 1408
#define NM 16

typedef unsigned long long ull;

// SwiGLU intermediate scratch: [E, M, F] fp32 = 5.77 MB
__device__ float g_inter[(size_t)NE * NM * NF];
// down-proj partial sums: [2, E, M, H] fp32 = 16.8 MB
__device__ float g_part[(size_t)2 * NE * NM * NH];

__device__ __forceinline__ ull pack2(float lo, float hi) {
    ull r;
    asm("mov.b64 %0, {%1, %2};" : "=l"(r) : "f"(lo), "f"(hi));
    return r;
}
__device__ __forceinline__ void fma2(ull& d, ull a, ull b) {
    asm("fma.rn.f32x2 %0, %1, %2, %0;" : "+l"(d) : "l"(a), "l"(b));
}
__device__ __forceinline__ float2 unpack2(ull v) {
    float2 r;
    asm("mov.b64 {%0, %1}, %2;" : "=f"(r.x), "=f"(r.y) : "l"(v));
    return r;
}

#define CP_ASYNC_8(dst32, src)  asm volatile("cp.async.ca.shared.global [%0], [%1], 8;"  :: "r"(dst32), "l"(src))
#define CP_ASYNC_16(dst32, src) asm volatile("cp.async.cg.shared.global [%0], [%1], 16;" :: "r"(dst32), "l"(src))
#define CP_COMMIT()   asm volatile("cp.async.commit_group;")
#define CP_WAIT(n)    asm volatile("cp.async.wait_group %0;" :: "n"(n))
#define CP_WAIT_ALL() asm volatile("cp.async.wait_all;")

#define XS_PAD 20   // 80B row stride, 16B-aligned for LDS.128

// ---------------------------------------------------------------------------
// Kernel 1: inter = silu(x@gate) * (x@up).  64 thr/CTA, 2 f-cols/thread.
// Weights streamed via cp.async into an 8-stage smem ring (stage = 2 h-steps,
// 32B/thread/stage), issue distance 6.  Each thread produces & consumes only
// its own slots -> no intra-pipeline syncthreads.  grid (11, 64).
// ---------------------------------------------------------------------------
#define K1_CHUNK 256
#define K1_NBLK (NH / 2)        // 1024 blocks of 2 h-steps
#define K1_CBLK (K1_CHUNK / 2)  // 128 blocks per xs chunk

#define K1_COMP(gv, uv, hrow) do {                                             \
    ull bg0 = pack2((gv).x, (gv).x), bg1 = pack2((gv).y, (gv).y);              \
    ull bu0 = pack2((uv).x, (uv).x), bu1 = pack2((uv).y, (uv).y);              \
    const ulonglong2* xr = reinterpret_cast<const ulonglong2*>(&xs[hrow][0]);  \
    ulonglong2 x01 = xr[0], x23 = xr[1], x45 = xr[2], x67 = xr[3];             \
    fma2(accg[0][0], x01.x, bg0); fma2(accg[1][0], x01.x, bg1);                \
    fma2(accu[0][0], x01.x, bu0); fma2(accu[1][0], x01.x, bu1);                \
    fma2(accg[0][1], x01.y, bg0); fma2(accg[1][1], x01.y, bg1);                \
    fma2(accu[0][1], x01.y, bu0); fma2(accu[1][1], x01.y, bu1);                \
    fma2(accg[0][2], x23.x, bg0); fma2(accg[1][2], x23.x, bg1);                \
    fma2(accu[0][2], x23.x, bu0); fma2(accu[1][2], x23.x, bu1);                \
    fma2(accg[0][3], x23.y, bg0); fma2(accg[1][3], x23.y, bg1);                \
    fma2(accu[0][3], x23.y, bu0); fma2(accu[1][3], x23.y, bu1);                \
    fma2(accg[0][4], x45.x, bg0); fma2(accg[1][4], x45.x, bg1);                \
    fma2(accu[0][4], x45.x, bu0); fma2(accu[1][4], x45.x, bu1);                \
    fma2(accg[0][5], x45.y, bg0); fma2(accg[1][5], x45.y, bg1);                \
    fma2(accu[0][5], x45.y, bu0); fma2(accu[1][5], x45.y, bu1);                \
    fma2(accg[0][6], x67.x, bg0); fma2(accg[1][6], x67.x, bg1);                \
    fma2(accu[0][6], x67.x, bu0); fma2(accu[1][6], x67.x, bu1);                \
    fma2(accg[0][7], x67.y, bg0); fma2(accg[1][7], x67.y, bg1);                \
    fma2(accu[0][7], x67.y, bu0); fma2(accu[1][7], x67.y, bu1);                \
} while (0)

// issue stage for h-block bi (2 h-steps): 4 x cp.async 8B, one commit group
#define K1_ISSUE(bi) do {                                                      \
    const int _b = (bi) < K1_NBLK ? (bi) : K1_NBLK - 1;                        \
    const int _s = (bi) & 7;                                                   \
    const float* _g = gp + (size_t)(_b * 2) * NF;                              \
    const float* _u = upp + (size_t)(_b * 2) * NF;                             \
    CP_ASYNC_8((unsigned)__cvta_generic_to_shared(&wgs[_s][0][tid]), _g);      \
    CP_ASYNC_8((unsigned)__cvta_generic_to_shared(&wgs[_s][1][tid]), _g + NF); \
    CP_ASYNC_8((unsigned)__cvta_generic_to_shared(&wus[_s][0][tid]), _u);      \
    CP_ASYNC_8((unsigned)__cvta_generic_to_shared(&wus[_s][1][tid]), _u + NF); \
    CP_COMMIT();                                                               \
} while (0)

__global__ __launch_bounds__(64) void moe_gateup_kernel(
    const float* __restrict__ x,
    const float* __restrict__ gate,
    const float* __restrict__ up)
{
    __shared__ float xs[K1_CHUNK][XS_PAD];        // 20480 B
    __shared__ float2 wgs[8][2][64];              // 8192 B
    __shared__ float2 wus[8][2][64];              // 8192 B

    const int e = blockIdx.y;
    const int tid = threadIdx.x;
    const int f = blockIdx.x * 128 + tid * 2;

    const float* xe = x + (size_t)e * NM * NH;
    const float* gp = gate + (size_t)e * NH * NF + f;
    const float* upp = up + (size_t)e * NH * NF + f;

    ull accg[2][8], accu[2][8];
#pragma unroll
    for (int c = 0; c < 2; c++)
#pragma unroll
        for (int j = 0; j < 8; j++) { accg[c][j] = 0ull; accu[c][j] = 0ull; }

    // prologue: 6 stages in flight
#pragma unroll
    for (int i = 0; i < 6; i++) K1_ISSUE(i);

    int bg = 0;
    for (int hc = 0; hc < NH; hc += K1_CHUNK) {
        __syncthreads();
#pragma unroll
        for (int mm = 0; mm < NM; mm++) {
#pragma unroll
            for (int hh = tid; hh < K1_CHUNK; hh += 64)
                xs[hh][mm] = xe[(size_t)mm * NH + hc + hh];
        }
        __syncthreads();

        for (int bl = 0; bl < K1_CBLK; bl++, bg++) {
            CP_WAIT(5);                        // group for block bg complete
            const int s = bg & 7;
            float2 g0v = wgs[s][0][tid];
            float2 u0v = wus[s][0][tid];
            float2 g1v = wgs[s][1][tid];
            float2 u1v = wus[s][1][tid];
            K1_COMP(g0v, u0v, bl * 2);
            K1_COMP(g1v, u1v, bl * 2 + 1);
            K1_ISSUE(bg + 6);
        }
    }
    CP_WAIT_ALL();

    float* ip = g_inter + (size_t)e * NM * NF + f;
#pragma unroll
    for (int j = 0; j < 8; j++) {
        float2 g0v = unpack2(accg[0][j]), g1v = unpack2(accg[1][j]);
        float2 u0v = unpack2(accu[0][j]), u1v = unpack2(accu[1][j]);
        float2 o_m0, o_m1;
        o_m0.x = g0v.x / (1.0f + __expf(-g0v.x)) * u0v.x;
        o_m0.y = g1v.x / (1.0f + __expf(-g1v.x)) * u1v.x;
        o_m1.x = g0v.y / (1.0f + __expf(-g0v.y)) * u0v.y;
        o_m1.y = g1v.y / (1.0f + __expf(-g1v.y)) * u1v.y;
        *reinterpret_cast<float2*>(ip + (size_t)(2 * j) * NF)     = o_m0;
        *reinterpret_cast<float2*>(ip + (size_t)(2 * j + 1) * NF) = o_m1;
    }
}

// ---------------------------------------------------------------------------
// Kernel 2: partial down-proj.  64 thr/CTA, 4 h-cols/thread, F-split 2.
// Weights streamed via cp.async 16B, 8-stage ring (stage = 2 f-steps),
// issue distance 6.  grid (8, 64, 2).
// ---------------------------------------------------------------------------
#define K2_CHUNK 352
#define K2_FSPLIT 704
#define K2_NBLK (K2_FSPLIT / 2)   // 352 blocks of 2 f-steps
#define K2_CBLK (K2_CHUNK / 2)    // 176 blocks per xs chunk

#define K2_COMP(wv, hrow) do {                                                 \
    ull b0 = pack2((wv).x, (wv).x), b1w = pack2((wv).y, (wv).y);               \
    ull b2w = pack2((wv).z, (wv).z), b3 = pack2((wv).w, (wv).w);               \
    const ulonglong2* xr = reinterpret_cast<const ulonglong2*>(&xs[hrow][0]);  \
    ulonglong2 x01 = xr[0], x23 = xr[1], x45 = xr[2], x67 = xr[3];             \
    fma2(acc[0][0], x01.x, b0);  fma2(acc[1][0], x01.x, b1w);                  \
    fma2(acc[2][0], x01.x, b2w); fma2(acc[3][0], x01.x, b3);                   \
    fma2(acc[0][1], x01.y, b0);  fma2(acc[1][1], x01.y, b1w);                  \
    fma2(acc[2][1], x01.y, b2w); fma2(acc[3][1], x01.y, b3);                   \
    fma2(acc[0][2], x23.x, b0);  fma2(acc[1][2], x23.x, b1w);                  \
    fma2(acc[2][2], x23.x, b2w); fma2(acc[3][2], x23.x, b3);                   \
    fma2(acc[0][3], x23.y, b0);  fma2(acc[1][3], x23.y, b1w);                  \
    fma2(acc[2][3], x23.y, b2w); fma2(acc[3][3], x23.y, b3);                   \
    fma2(acc[0][4], x45.x, b0);  fma2(acc[1][4], x45.x, b1w);                  \
    fma2(acc[2][4], x45.x, b2w); fma2(acc[3][4], x45.x, b3);                   \
    fma2(acc[0][5], x45.y, b0);  fma2(acc[1][5], x45.y, b1w);                  \
    fma2(acc[2][5], x45.y, b2w); fma2(acc[3][5], x45.y, b3);                   \
    fma2(acc[0][6], x67.x, b0);  fma2(acc[1][6], x67.x, b1w);                  \
    fma2(acc[2][6], x67.x, b2w); fma2(acc[3][6], x67.x, b3);                   \
    fma2(acc[0][7], x67.y, b0);  fma2(acc[1][7], x67.y, b1w);                  \
    fma2(acc[2][7], x67.y, b2w); fma2(acc[3][7], x67.y, b3);                   \
} while (0)

#define K2_ISSUE(bi) do {                                                      \
    const int _b = (bi) < K2_NBLK ? (bi) : K2_NBLK - 1;                        \
    const int _s = (bi) & 7;                                                   \
    const float* _d = dp + (size_t)(_b * 2) * NH;                              \
    CP_ASYNC_16((unsigned)__cvta_generic_to_shared(&wds[_s][0][tid]), _d);     \
    CP_ASYNC_16((unsigned)__cvta_generic_to_shared(&wds[_s][1][tid]), _d + NH);\
    CP_COMMIT();                                                               \
} while (0)

__global__ __launch_bounds__(64) void moe_down_kernel(
    const float* __restrict__ down)
{
    __shared__ float xs[K2_CHUNK][XS_PAD];     // 28160 B
    __shared__ float4 wds[8][2][64];           // 16384 B

    const int e = blockIdx.y;
    const int z = blockIdx.z;
    const int tid = threadIdx.x;
    const int h0 = blockIdx.x * 256 + tid * 4;

    const float* ie = g_inter + (size_t)e * NM * NF + (size_t)z * K2_FSPLIT;
    const float* dp = down + (size_t)e * NF * NH + (size_t)z * K2_FSPLIT * NH + h0;

    ull acc[4][8];
#pragma unroll
    for (int c = 0; c < 4; c++)
#pragma unroll
        for (int j = 0; j < 8; j++) acc[c][j] = 0ull;

#pragma unroll
    for (int i = 0; i < 6; i++) K2_ISSUE(i);

    int bg = 0;
    for (int fc = 0; fc < K2_FSPLIT; fc += K2_CHUNK) {
        __syncthreads();
#pragma unroll
        for (int mm = 0; mm < NM; mm++) {
            for (int hh = tid; hh < K2_CHUNK; hh += 64)
                xs[hh][mm] = ie[(size_t)mm * NF + fc + hh];
        }
        __syncthreads();

        for (int bl = 0; bl < K2_CBLK; bl++, bg++) {
            CP_WAIT(5);
            const int s = bg & 7;
            float4 w0 = wds[s][0][tid];
            float4 w1 = wds[s][1][tid];
            K2_COMP(w0, bl * 2);
            K2_COMP(w1, bl * 2 + 1);
            K2_ISSUE(bg + 6);
        }
    }
    CP_WAIT_ALL();

    float* pp = g_part + ((size_t)z * NE * NM + (size_t)e * NM) * NH + h0;
#pragma unroll
    for (int j = 0; j < 8; j++) {
        float2 r0 = unpack2(acc[0][j]), r1 = unpack2(acc[1][j]);
        float2 r2 = unpack2(acc[2][j]), r3 = unpack2(acc[3][j]);
        float4 v0 = make_float4(r0.x, r1.x, r2.x, r3.x);
        float4 v1 = make_float4(r0.y, r1.y, r2.y, r3.y);
        *reinterpret_cast<float4*>(pp + (size_t)(2 * j) * NH)     = v0;
        *reinterpret_cast<float4*>(pp + (size_t)(2 * j + 1) * NH) = v1;
    }
}

// ---------------------------------------------------------------------------
// Kernel 3: out = part[0] + part[1]
// ---------------------------------------------------------------------------
__global__ __launch_bounds__(256) void moe_reduce_kernel(float* __restrict__ out)
{
    const size_t i = (size_t)blockIdx.x * 256 + threadIdx.x;   // float4 index
    const size_t n4 = (size_t)NE * NM * NH / 4;
    if (i < n4) {
        const float4* p0 = reinterpret_cast<const float4*>(g_part);
        const float4* p1 = reinterpret_cast<const float4*>(g_part + (size_t)NE * NM * NH);
        float4 a = p0[i], b = p1[i];
        float4 r = make_float4(a.x + b.x, a.y + b.y, a.z + b.z, a.w + b.w);
        reinterpret_cast<float4*>(out)[i] = r;
    }
}

extern "C" void kernel_launch(void* const* d_in, const int* in_sizes, int n_in,
                              void* d_out, int out_size)
{
    const float* x    = (const float*)d_in[0];  // [T=1024, H=2048]
    const float* gate = (const float*)d_in[1];  // [E, H, F]
    const float* up   = (const float*)d_in[2];  // [E, H, F]
    const float* down = (const float*)d_in[3];  // [E, F, H]
    float* out = (float*)d_out;                 // [T, H] fp32

    dim3 g1(NF / 128, NE);        // 11 x 64 = 704 CTAs, 64 thr
    moe_gateup_kernel<<<g1, 64>>>(x, gate, up);

    dim3 g2(NH / 256, NE, 2);     // 8 x 64 x 2 = 1024 CTAs, 64 thr
    moe_down_kernel<<<g2, 64>>>(down);

    const int n4 = NE * NM * NH / 4;              // 524288
    moe_reduce_kernel<<<(n4 + 255) / 256, 256>>>(out);
}